// round 9
// baseline (speedup 1.0000x reference)
#include <cuda_runtime.h>
#include <stdint.h>

#define MAXN 50000
#define MAXE 800000
#define MAXF 216
#define NGRAPHS 64

// ---------------- scratch (static device globals; allocation-free) ----------------
__device__ __align__(16) float g_h[(size_t)MAXN * MAXF];    // layer outputs (padded stride)
__device__ __align__(16) float g_agg[(size_t)MAXN * MAXF];  // aggregated features (padded stride)
__device__ int   g_cnt[MAXN];
__device__ int   g_rowptr[MAXN + 1];
__device__ int   g_cursor[MAXN];
__device__ __align__(16) int2 g_csr[MAXE];                  // packed {src, w-as-int}
__device__ float g_dinv[MAXN];
__device__ int   g_starts[NGRAPHS + 1];
__device__ int   g_idx64;   // 1 if index arrays are int64, 0 if int32

// ---------------- index dtype detection ----------------
__global__ void k_detect(const int* __restrict__ w) {
    if (threadIdx.x == 0 && blockIdx.x == 0) {
        int is64 = 1;
        #pragma unroll 1
        for (int i = 1; i < 128; i += 2)
            if (w[i] != 0) { is64 = 0; break; }
        g_idx64 = is64;
    }
}

__device__ __forceinline__ int idx_at(const void* p, long long i, int is64) {
    return is64 ? (int)((const long long*)p)[i] : ((const int*)p)[i];
}

// ---------------- zero kernels ----------------
__global__ void k_zero_i(int* p, int n) {
    int i = blockIdx.x * blockDim.x + threadIdx.x;
    if (i < n) p[i] = 0;
}

// zero only invalid tail rows of the dense output
__global__ void k_zero_tail(float4* __restrict__ out4, const int* __restrict__ starts,
                            int max_num, int FO, int Ntot) {
    int g = blockIdx.y;
    int s0 = starts[g];
    int s1 = (g == NGRAPHS - 1) ? Ntot : starts[g + 1];
    int valid = s1 - s0; if (valid > max_num) valid = max_num;
    size_t rowq = (size_t)FO / 4;
    size_t base = ((size_t)g * max_num + valid) * rowq;
    size_t end  = ((size_t)(g + 1) * max_num) * rowq;
    float4 z = {0.f, 0.f, 0.f, 0.f};
    size_t i = base + blockIdx.x * blockDim.x + threadIdx.x;
    size_t stride = (size_t)gridDim.x * blockDim.x;
    for (; i < end; i += stride) out4[i] = z;
}

// ---------------- CSR build ----------------
__global__ void k_count(const void* __restrict__ ei, int* cnt, int E, int N) {
    int is64 = g_idx64;
    int i = blockIdx.x * blockDim.x + threadIdx.x;
    if (i < E) {
        int d = idx_at(ei, (long long)E + i, is64);
        if (d >= 0 && d < N) atomicAdd(&cnt[d], 1);
    }
}

__global__ void k_scan(const int* __restrict__ cnt, int* rowptr, int* cursor,
                       float* dinv, int n) {
    __shared__ int s[1024];
    int tid = threadIdx.x;
    int chunk = (n + 1023) / 1024;
    int lo = tid * chunk;
    int hi = lo + chunk; if (hi > n) hi = n;
    if (lo > n) lo = n;
    int sum = 0;
    for (int i = lo; i < hi; i++) sum += cnt[i];
    s[tid] = sum;
    __syncthreads();
    for (int off = 1; off < 1024; off <<= 1) {
        int t = (tid >= off) ? s[tid - off] : 0;
        __syncthreads();
        s[tid] += t;
        __syncthreads();
    }
    int run = s[tid] - sum;
    for (int i = lo; i < hi; i++) {
        int v = cnt[i];
        rowptr[i] = run;
        cursor[i] = run;
        dinv[i] = rsqrtf((float)v + 1.0f);
        run += v;
    }
    if (tid == 1023) rowptr[n] = run;
}

__global__ void k_fill(const void* __restrict__ ei,
                       const float* __restrict__ dinv, int* cursor,
                       int2* __restrict__ csr, int E, int N) {
    int is64 = g_idx64;
    int e = blockIdx.x * blockDim.x + threadIdx.x;
    if (e < E) {
        int s = idx_at(ei, e, is64);
        int d = idx_at(ei, (long long)E + e, is64);
        if (s >= 0 && s < N && d >= 0 && d < N) {
            int pos = atomicAdd(&cursor[d], 1);
            float w = dinv[s] * dinv[d];
            csr[pos] = make_int2(s, __float_as_int(w));
        }
    }
}

// starts[g] = first index i with batch[i] >= g
__global__ void k_starts(const void* __restrict__ batch, int n, int* starts) {
    int is64 = g_idx64;
    int g = threadIdx.x;
    if (g < NGRAPHS) {
        int lo = 0, hi = n;
        while (lo < hi) {
            int mid = (lo + hi) >> 1;
            if (idx_at(batch, mid, is64) < g) lo = mid + 1; else hi = mid;
        }
        starts[g] = lo;
    }
}

// ---------------- aggregation: float2 lanes (layer 1, unpadded input) ----------------
template <int LANES, int GS>
__global__ __launch_bounds__(256) void k_agg_f2(const float2* __restrict__ h2,
                                                int in_s2, int out_s2,
                                                const int* __restrict__ rowptr,
                                                const int2* __restrict__ csr,
                                                const float* __restrict__ dinv,
                                                float2* __restrict__ agg2, int Nn) {
    int gid = threadIdx.x / GS;
    int lane = threadIdx.x % GS;
    int node = blockIdx.x * (256 / GS) + gid;
    if (node >= Nn) return;
    int e0 = rowptr[node], e1 = rowptr[node + 1];
    float ax = 0.f, ay = 0.f;
    bool act = lane < LANES;
    int t = e0;
    for (; t + 8 <= e1; t += 8) {
        int2 ew[8];
        #pragma unroll
        for (int u = 0; u < 8; u++) ew[u] = csr[t + u];
        if (act) {
            float2 v[8];
            #pragma unroll
            for (int u = 0; u < 8; u++) v[u] = h2[(size_t)ew[u].x * in_s2 + lane];
            #pragma unroll
            for (int u = 0; u < 8; u++) {
                float w = __int_as_float(ew[u].y);
                ax += w * v[u].x; ay += w * v[u].y;
            }
        }
    }
    for (; t < e1; t++) {
        int2 ew = csr[t];
        if (act) {
            float w = __int_as_float(ew.y);
            float2 v = h2[(size_t)ew.x * in_s2 + lane];
            ax += w * v.x; ay += w * v.y;
        }
    }
    if (act) {
        float d = dinv[node];
        float2 self = h2[(size_t)node * in_s2 + lane];
        float2 r;
        r.x = ax + d * d * self.x;
        r.y = ay + d * d * self.y;
        agg2[(size_t)node * out_s2 + lane] = r;
    }
}

// ---------------- aggregation: float4 lanes (padded intermediates) ----------------
template <int LANES4, int GS>
__global__ __launch_bounds__(256) void k_agg_f4(const float4* __restrict__ h4,
                                                int s4,  // stride in float4 (in == out)
                                                const int* __restrict__ rowptr,
                                                const int2* __restrict__ csr,
                                                const float* __restrict__ dinv,
                                                float4* __restrict__ agg4, int Nn) {
    int gid = threadIdx.x / GS;
    int lane = threadIdx.x % GS;
    int node = blockIdx.x * (256 / GS) + gid;
    if (node >= Nn) return;
    int e0 = rowptr[node], e1 = rowptr[node + 1];
    float ax = 0.f, ay = 0.f, az = 0.f, aw = 0.f;
    bool act = lane < LANES4;
    int t = e0;
    for (; t + 8 <= e1; t += 8) {
        int2 ew[8];
        #pragma unroll
        for (int u = 0; u < 8; u++) ew[u] = csr[t + u];
        if (act) {
            float4 v[8];
            #pragma unroll
            for (int u = 0; u < 8; u++) v[u] = h4[(size_t)ew[u].x * s4 + lane];
            #pragma unroll
            for (int u = 0; u < 8; u++) {
                float w = __int_as_float(ew[u].y);
                ax += w * v[u].x; ay += w * v[u].y;
                az += w * v[u].z; aw += w * v[u].w;
            }
        }
    }
    for (; t < e1; t++) {
        int2 ew = csr[t];
        if (act) {
            float w = __int_as_float(ew.y);
            float4 v = h4[(size_t)ew.x * s4 + lane];
            ax += w * v.x; ay += w * v.y; az += w * v.z; aw += w * v.w;
        }
    }
    if (act) {
        float d = dinv[node];
        float d2 = d * d;
        float4 self = h4[(size_t)node * s4 + lane];
        float4 r;
        r.x = ax + d2 * self.x;
        r.y = ay + d2 * self.y;
        r.z = az + d2 * self.z;
        r.w = aw + d2 * self.w;
        agg4[(size_t)node * s4 + lane] = r;
    }
}

// generic fallback (any F, stride = F in & out)
__global__ void k_aggregate(const float* __restrict__ h,
                            const int* __restrict__ rowptr,
                            const int2* __restrict__ csr,
                            const float* __restrict__ dinv,
                            float* __restrict__ agg, int F) {
    int i = blockIdx.x;
    int f = threadIdx.x;
    int e0 = rowptr[i], e1 = rowptr[i + 1];
    float acc = 0.f;
    if (f < F) {
        for (int t = e0; t < e1; t++) {
            int2 ew = csr[t];
            acc += h[(size_t)ew.x * F + f] * __int_as_float(ew.y);
        }
        float d = dinv[i];
        agg[(size_t)i * F + f] = acc + d * d * h[(size_t)i * F + f];
    }
}

// ---------------- tf32 tensor-core GEMM (strided A/C) ----------------
__device__ __forceinline__ float to_tf32(float x) {
    float y;
    asm("cvt.rna.tf32.f32 %0, %1;" : "=f"(y) : "f"(x));
    return y;
}

__device__ __forceinline__ void mma_tf32(float& d0, float& d1, float& d2, float& d3,
                                         float a0, float a1, float a2, float a3,
                                         float b0, float b1) {
    asm("mma.sync.aligned.m16n8k8.row.col.f32.tf32.tf32.f32 "
        "{%0,%1,%2,%3},{%4,%5,%6,%7},{%8,%9},{%0,%1,%2,%3};"
        : "+f"(d0), "+f"(d1), "+f"(d2), "+f"(d3)
        : "r"(__float_as_uint(a0)), "r"(__float_as_uint(a1)),
          "r"(__float_as_uint(a2)), "r"(__float_as_uint(a3)),
          "r"(__float_as_uint(b0)), "r"(__float_as_uint(b1)));
}

// MODE 0: C = relu(A@B + bias), row stride ldc.  MODE 1: dense-batch remap.
template <int MODE>
__global__ __launch_bounds__(256) void k_gemm_tc(const float* __restrict__ A,
                                                 const float* __restrict__ B,
                                                 const float* __restrict__ bias,
                                                 const void* __restrict__ batch,
                                                 const int* __restrict__ starts,
                                                 float* __restrict__ C,
                                                 int M, int K, int N,
                                                 int lda, int ldc, int max_num) {
    __shared__ float As[16][132];
    __shared__ float Bs[16][68];
    int tid = threadIdx.x;
    int warp = tid >> 5, lane = tid & 31;
    int wm = warp >> 2, wn = warp & 3;
    int gid = lane >> 2, t4 = lane & 3;
    int row0 = blockIdx.y * 128, col0 = blockIdx.x * 64;

    float acc[4][2][4];
    #pragma unroll
    for (int mt = 0; mt < 4; mt++)
        #pragma unroll
        for (int nt = 0; nt < 2; nt++)
            #pragma unroll
            for (int r = 0; r < 4; r++) acc[mt][nt][r] = 0.f;

    for (int kk = 0; kk < K; kk += 16) {
        {
            int r = tid >> 1;
            int kbase = (tid & 1) * 8;
            int grow = row0 + r;
            #pragma unroll
            for (int j = 0; j < 8; j++) {
                int gk = kk + kbase + j;
                float v = (grow < M && gk < K) ? A[(size_t)grow * lda + gk] : 0.f;
                As[kbase + j][r] = to_tf32(v);
            }
        }
        #pragma unroll
        for (int rl = 0; rl < 4; rl++) {
            int idx = tid + rl * 256;
            int br = idx >> 6, bc = idx & 63;
            int gk = kk + br, gc = col0 + bc;
            float v = (gk < K && gc < N) ? B[(size_t)gk * N + gc] : 0.f;
            Bs[br][bc] = to_tf32(v);
        }
        __syncthreads();
        #pragma unroll
        for (int k8 = 0; k8 < 16; k8 += 8) {
            float bf[2][2];
            #pragma unroll
            for (int nt = 0; nt < 2; nt++) {
                int bc = wn * 16 + nt * 8 + gid;
                bf[nt][0] = Bs[k8 + t4][bc];
                bf[nt][1] = Bs[k8 + t4 + 4][bc];
            }
            #pragma unroll
            for (int mt = 0; mt < 4; mt++) {
                int ar = wm * 64 + mt * 16 + gid;
                float a0 = As[k8 + t4][ar];
                float a1 = As[k8 + t4][ar + 8];
                float a2 = As[k8 + t4 + 4][ar];
                float a3 = As[k8 + t4 + 4][ar + 8];
                #pragma unroll
                for (int nt = 0; nt < 2; nt++)
                    mma_tf32(acc[mt][nt][0], acc[mt][nt][1], acc[mt][nt][2], acc[mt][nt][3],
                             a0, a1, a2, a3, bf[nt][0], bf[nt][1]);
            }
        }
        __syncthreads();
    }

    int is64 = (MODE == 1) ? g_idx64 : 0;
    #pragma unroll
    for (int mt = 0; mt < 4; mt++) {
        #pragma unroll
        for (int half = 0; half < 2; half++) {
            int row = row0 + wm * 64 + mt * 16 + gid + half * 8;
            if (row >= M) continue;
            float* orow;
            if (MODE == 0) {
                orow = C + (size_t)row * ldc;
            } else {
                int bg = idx_at(batch, row, is64);
                int pos = row - starts[bg];
                if (pos >= max_num) continue;
                orow = C + ((size_t)bg * max_num + pos) * N;
            }
            #pragma unroll
            for (int nt = 0; nt < 2; nt++) {
                int col = col0 + wn * 16 + nt * 8 + t4 * 2;
                #pragma unroll
                for (int c = 0; c < 2; c++) {
                    if (col + c < N) {
                        float v = acc[mt][nt][half * 2 + c] + bias[col + c];
                        if (MODE == 0) v = fmaxf(v, 0.f);
                        orow[col + c] = v;
                    }
                }
            }
        }
    }
}

// ---------------- host launcher ----------------
extern "C" void kernel_launch(void* const* d_in, const int* in_sizes, int n_in,
                              void* d_out, int out_size) {
    const float* x     = (const float*)d_in[0];
    const void*  ei    = d_in[1];
    const void*  batch = d_in[2];
    const float* W1 = (const float*)d_in[4];
    const float* b1 = (const float*)d_in[5];
    const float* W2 = (const float*)d_in[6];
    const float* b2 = (const float*)d_in[7];
    const float* W3 = (const float*)d_in[8];
    const float* b3 = (const float*)d_in[9];
    const float* Wf = (const float*)d_in[10];
    const float* bf = (const float*)d_in[11];
    float* out = (float*)d_out;

    int N  = in_sizes[2];            // nodes
    int E  = in_sizes[1] / 2;        // edges
    int F0 = in_sizes[0] / N;        // 54
    int F2 = in_sizes[6] / F0;       // 108
    int F3 = in_sizes[8] / F2;       // 216
    int FO = in_sizes[10] / F3;      // 200
    int max_num = out_size / (NGRAPHS * FO);

    bool fast = (F0 == 54 && F2 == 108 && F3 == 216);
    int F0p = fast ? 56 : F0;    // padded strides
    int F2p = fast ? 112 : F2;
    int F3p = F3;

    float *p_h, *p_agg, *p_dinv;
    int *p_cnt, *p_rowptr, *p_cursor, *p_starts;
    int2* p_csr;
    cudaGetSymbolAddress((void**)&p_h, g_h);
    cudaGetSymbolAddress((void**)&p_agg, g_agg);
    cudaGetSymbolAddress((void**)&p_dinv, g_dinv);
    cudaGetSymbolAddress((void**)&p_cnt, g_cnt);
    cudaGetSymbolAddress((void**)&p_rowptr, g_rowptr);
    cudaGetSymbolAddress((void**)&p_cursor, g_cursor);
    cudaGetSymbolAddress((void**)&p_csr, g_csr);
    cudaGetSymbolAddress((void**)&p_starts, g_starts);

    const int T = 256;
    int nb_n = (N + T - 1) / T;
    int nb_e = (E + T - 1) / T;

    k_detect<<<1, 32>>>((const int*)ei);
    k_starts<<<1, NGRAPHS>>>(batch, N, p_starts);
    {
        dim3 zgrid(32, NGRAPHS);
        k_zero_tail<<<zgrid, T>>>((float4*)out, p_starts, max_num, FO, N);
    }

    // CSR build + normalization
    k_zero_i<<<nb_n, T>>>(p_cnt, N);
    k_count<<<nb_e, T>>>(ei, p_cnt, E, N);
    k_scan<<<1, 1024>>>(p_cnt, p_rowptr, p_cursor, p_dinv, N);
    k_fill<<<nb_e, T>>>(ei, p_dinv, p_cursor, p_csr, E, N);

    int mb = (N + 127) / 128;

    if (fast) {
        // ---- layer 1: agg(x:54) -> agg[56]; GEMM K=54 -> h[56] ----
        k_agg_f2<27, 32><<<(N + 7) / 8, T>>>((const float2*)x, 27, 28,
                                             p_rowptr, p_csr, p_dinv,
                                             (float2*)p_agg, N);
        {
            dim3 grid(1, mb);
            k_gemm_tc<0><<<grid, T>>>(p_agg, W1, b1, nullptr, nullptr, p_h,
                                      N, 54, 54, 56, 56, 0);
        }
        // ---- layer 2: agg(h[56]) float4 14 lanes, GS=16 -> agg[56]; GEMM -> h[112] ----
        k_agg_f4<14, 16><<<(N + 15) / 16, T>>>((const float4*)p_h, 14,
                                               p_rowptr, p_csr, p_dinv,
                                               (float4*)p_agg, N);
        {
            dim3 grid(2, mb);
            k_gemm_tc<0><<<grid, T>>>(p_agg, W2, b2, nullptr, nullptr, p_h,
                                      N, 54, 108, 56, 112, 0);
        }
        // ---- layer 3: agg(h[112]) float4 28 lanes, GS=32 -> agg[112]; GEMM -> h[216] ----
        k_agg_f4<28, 32><<<(N + 7) / 8, T>>>((const float4*)p_h, 28,
                                             p_rowptr, p_csr, p_dinv,
                                             (float4*)p_agg, N);
        {
            dim3 grid(4, mb);
            k_gemm_tc<0><<<grid, T>>>(p_agg, W3, b3, nullptr, nullptr, p_h,
                                      N, 108, 216, 112, 216, 0);
        }
    } else {
        // generic fallback path (unpadded strides)
        k_aggregate<<<N, ((F0 + 31) / 32) * 32>>>(x, p_rowptr, p_csr, p_dinv, p_agg, F0);
        {
            dim3 grid((F0 + 63) / 64, mb);
            k_gemm_tc<0><<<grid, T>>>(p_agg, W1, b1, nullptr, nullptr, p_h,
                                      N, F0, F0, F0, F0, 0);
        }
        k_aggregate<<<N, ((F0 + 31) / 32) * 32>>>(p_h, p_rowptr, p_csr, p_dinv, p_agg, F0);
        {
            dim3 grid((F2 + 63) / 64, mb);
            k_gemm_tc<0><<<grid, T>>>(p_agg, W2, b2, nullptr, nullptr, p_h,
                                      N, F0, F2, F0, F2, 0);
        }
        k_aggregate<<<N, ((F2 + 31) / 32) * 32>>>(p_h, p_rowptr, p_csr, p_dinv, p_agg, F2);
        {
            dim3 grid((F3 + 63) / 64, mb);
            k_gemm_tc<0><<<grid, T>>>(p_agg, W3, b3, nullptr, nullptr, p_h,
                                      N, F2, F3, F2, F3, 0);
        }
    }

    // ---- final: h3 @ Wf + bf -> dense [64, max_num, FO] ----
    {
        dim3 grid((FO + 63) / 64, mb);
        k_gemm_tc<1><<<grid, T>>>(p_h, Wf, bf, batch, p_starts, out,
                                  N, F3, FO, F3p, FO, max_num);
    }
}

// round 10
// speedup vs baseline: 1.1742x; 1.1742x over previous
#include <cuda_runtime.h>
#include <stdint.h>

#define MAXN 50000
#define MAXE 800000
#define MAXFP 224
#define NGRAPHS 64

// ---------------- scratch (static device globals; allocation-free) ----------------
__device__ __align__(16) float g_h[(size_t)MAXN * MAXFP];    // layer outputs (padded stride)
__device__ __align__(16) float g_agg[(size_t)MAXN * MAXFP];  // aggregated features (padded stride)
__device__ int   g_cnt[MAXN];
__device__ int   g_rowptr[MAXN + 1];
__device__ int   g_cursor[MAXN];
__device__ __align__(16) int2 g_csr[MAXE];                   // packed {src, w-as-int}
__device__ float g_dinv[MAXN];
__device__ int   g_starts[NGRAPHS + 1];
__device__ int   g_idx64;

__device__ __forceinline__ int idx_at(const void* p, long long i, int is64) {
    return is64 ? (int)((const long long*)p)[i] : ((const int*)p)[i];
}

// ---------------- fused init: zero cnt + detect idx dtype + starts ----------------
__global__ void k_init(const int* __restrict__ eiw, const void* __restrict__ batch,
                       int* cnt, int* starts, int n) {
    if (blockIdx.x == gridDim.x - 1) {
        __shared__ int s_is64;
        if (threadIdx.x == 0) {
            int is64 = 1;
            #pragma unroll 1
            for (int i = 1; i < 128; i += 2)
                if (eiw[i] != 0) { is64 = 0; break; }
            g_idx64 = is64;
            s_is64 = is64;
        }
        __syncthreads();
        int is64 = s_is64;
        int g = threadIdx.x;
        if (g < NGRAPHS) {
            int lo = 0, hi = n;
            while (lo < hi) {
                int mid = (lo + hi) >> 1;
                if (idx_at(batch, mid, is64) < g) lo = mid + 1; else hi = mid;
            }
            starts[g] = lo;
        }
    } else {
        int i = blockIdx.x * blockDim.x + threadIdx.x;
        if (i < n) cnt[i] = 0;
    }
}

// zero only invalid tail rows of the dense output
__global__ void k_zero_tail(float4* __restrict__ out4, const int* __restrict__ starts,
                            int max_num, int FO, int Ntot) {
    int g = blockIdx.y;
    int s0 = starts[g];
    int s1 = (g == NGRAPHS - 1) ? Ntot : starts[g + 1];
    int valid = s1 - s0; if (valid > max_num) valid = max_num;
    size_t rowq = (size_t)FO / 4;
    size_t base = ((size_t)g * max_num + valid) * rowq;
    size_t end  = ((size_t)(g + 1) * max_num) * rowq;
    float4 z = {0.f, 0.f, 0.f, 0.f};
    size_t i = base + blockIdx.x * blockDim.x + threadIdx.x;
    size_t stride = (size_t)gridDim.x * blockDim.x;
    for (; i < end; i += stride) out4[i] = z;
}

// ---------------- CSR build ----------------
__global__ void k_count(const void* __restrict__ ei, int* cnt, int E, int N) {
    int is64 = g_idx64;
    int i = blockIdx.x * blockDim.x + threadIdx.x;
    if (i < E) {
        int d = idx_at(ei, (long long)E + i, is64);
        if (d >= 0 && d < N) atomicAdd(&cnt[d], 1);
    }
}

__global__ void k_scan(const int* __restrict__ cnt, int* rowptr, int* cursor,
                       float* dinv, int n) {
    __shared__ int s[1024];
    int tid = threadIdx.x;
    int chunk = (n + 1023) / 1024;
    int lo = tid * chunk;
    int hi = lo + chunk; if (hi > n) hi = n;
    if (lo > n) lo = n;
    int sum = 0;
    for (int i = lo; i < hi; i++) sum += cnt[i];
    s[tid] = sum;
    __syncthreads();
    for (int off = 1; off < 1024; off <<= 1) {
        int t = (tid >= off) ? s[tid - off] : 0;
        __syncthreads();
        s[tid] += t;
        __syncthreads();
    }
    int run = s[tid] - sum;
    for (int i = lo; i < hi; i++) {
        int v = cnt[i];
        rowptr[i] = run;
        cursor[i] = run;
        dinv[i] = rsqrtf((float)v + 1.0f);
        run += v;
    }
    if (tid == 1023) rowptr[n] = run;
}

__global__ void k_fill(const void* __restrict__ ei,
                       const float* __restrict__ dinv, int* cursor,
                       int2* __restrict__ csr, int E, int N) {
    int is64 = g_idx64;
    int e = blockIdx.x * blockDim.x + threadIdx.x;
    if (e < E) {
        int s = idx_at(ei, e, is64);
        int d = idx_at(ei, (long long)E + e, is64);
        if (s >= 0 && s < N && d >= 0 && d < N) {
            int pos = atomicAdd(&cursor[d], 1);
            float w = dinv[s] * dinv[d];
            csr[pos] = make_int2(s, __float_as_int(w));
        }
    }
}

// ---------------- aggregation: float2 lanes (layer 1, unpadded external input) ----------------
// Writes out stride OUT_S2 float2; lanes >= LANES write zeros (K-pad for GEMM).
template <int LANES, int OUT_S2>
__global__ __launch_bounds__(256) void k_agg_f2(const float2* __restrict__ h2,
                                                int in_s2,
                                                const int* __restrict__ rowptr,
                                                const int2* __restrict__ csr,
                                                const float* __restrict__ dinv,
                                                float2* __restrict__ agg2, int Nn) {
    const int GS = 32;
    int gid = threadIdx.x / GS;
    int lane = threadIdx.x % GS;
    int node = blockIdx.x * (256 / GS) + gid;
    if (node >= Nn) return;
    int e0 = rowptr[node], e1 = rowptr[node + 1];
    float ax = 0.f, ay = 0.f;
    bool act = lane < LANES;
    int t = e0;
    for (; t + 8 <= e1; t += 8) {
        int2 ew[8];
        #pragma unroll
        for (int u = 0; u < 8; u++) ew[u] = csr[t + u];
        if (act) {
            float2 v[8];
            #pragma unroll
            for (int u = 0; u < 8; u++) v[u] = h2[(size_t)ew[u].x * in_s2 + lane];
            #pragma unroll
            for (int u = 0; u < 8; u++) {
                float w = __int_as_float(ew[u].y);
                ax += w * v[u].x; ay += w * v[u].y;
            }
        }
    }
    for (; t < e1; t++) {
        int2 ew = csr[t];
        if (act) {
            float w = __int_as_float(ew.y);
            float2 v = h2[(size_t)ew.x * in_s2 + lane];
            ax += w * v.x; ay += w * v.y;
        }
    }
    float2 r = {0.f, 0.f};
    if (act) {
        float d = dinv[node];
        float2 self = h2[(size_t)node * in_s2 + lane];
        r.x = ax + d * d * self.x;
        r.y = ay + d * d * self.y;
    }
    agg2[(size_t)node * OUT_S2 + lane] = r;   // lanes >= LANES store zeros (pad)
}

// ---------------- aggregation: float4 lanes (padded intermediates, pads already zero) ----------------
template <int LANES4, int GS>
__global__ __launch_bounds__(256) void k_agg_f4(const float4* __restrict__ h4,
                                                int s4,
                                                const int* __restrict__ rowptr,
                                                const int2* __restrict__ csr,
                                                const float* __restrict__ dinv,
                                                float4* __restrict__ agg4, int Nn) {
    int gid = threadIdx.x / GS;
    int lane = threadIdx.x % GS;
    int node = blockIdx.x * (256 / GS) + gid;
    if (node >= Nn) return;
    int e0 = rowptr[node], e1 = rowptr[node + 1];
    float ax = 0.f, ay = 0.f, az = 0.f, aw = 0.f;
    bool act = lane < LANES4;
    int t = e0;
    for (; t + 8 <= e1; t += 8) {
        int2 ew[8];
        #pragma unroll
        for (int u = 0; u < 8; u++) ew[u] = csr[t + u];
        if (act) {
            float4 v[8];
            #pragma unroll
            for (int u = 0; u < 8; u++) v[u] = h4[(size_t)ew[u].x * s4 + lane];
            #pragma unroll
            for (int u = 0; u < 8; u++) {
                float w = __int_as_float(ew[u].y);
                ax += w * v[u].x; ay += w * v[u].y;
                az += w * v[u].z; aw += w * v[u].w;
            }
        }
    }
    for (; t < e1; t++) {
        int2 ew = csr[t];
        if (act) {
            float w = __int_as_float(ew.y);
            float4 v = h4[(size_t)ew.x * s4 + lane];
            ax += w * v.x; ay += w * v.y; az += w * v.z; aw += w * v.w;
        }
    }
    if (act) {
        float d = dinv[node];
        float d2 = d * d;
        float4 self = h4[(size_t)node * s4 + lane];
        float4 r;
        r.x = ax + d2 * self.x;
        r.y = ay + d2 * self.y;
        r.z = az + d2 * self.z;
        r.w = aw + d2 * self.w;
        agg4[(size_t)node * s4 + lane] = r;
    }
}

// generic fallback (any F, stride = F)
__global__ void k_aggregate(const float* __restrict__ h,
                            const int* __restrict__ rowptr,
                            const int2* __restrict__ csr,
                            const float* __restrict__ dinv,
                            float* __restrict__ agg, int F) {
    int i = blockIdx.x;
    int f = threadIdx.x;
    int e0 = rowptr[i], e1 = rowptr[i + 1];
    float acc = 0.f;
    if (f < F) {
        for (int t = e0; t < e1; t++) {
            int2 ew = csr[t];
            acc += h[(size_t)ew.x * F + f] * __int_as_float(ew.y);
        }
        float d = dinv[i];
        agg[(size_t)i * F + f] = acc + d * d * h[(size_t)i * F + f];
    }
}

// ---------------- tf32 tensor-core GEMM, BM=128 BN=128 BK=16 ----------------
__device__ __forceinline__ float to_tf32(float x) {
    float y;
    asm("cvt.rna.tf32.f32 %0, %1;" : "=f"(y) : "f"(x));
    return y;
}

__device__ __forceinline__ void mma_tf32(float& d0, float& d1, float& d2, float& d3,
                                         float a0, float a1, float a2, float a3,
                                         float b0, float b1) {
    asm("mma.sync.aligned.m16n8k8.row.col.f32.tf32.tf32.f32 "
        "{%0,%1,%2,%3},{%4,%5,%6,%7},{%8,%9},{%0,%1,%2,%3};"
        : "+f"(d0), "+f"(d1), "+f"(d2), "+f"(d3)
        : "r"(__float_as_uint(a0)), "r"(__float_as_uint(a1)),
          "r"(__float_as_uint(a2)), "r"(__float_as_uint(a3)),
          "r"(__float_as_uint(b0)), "r"(__float_as_uint(b1)));
}

// MODE 0: C = relu(A@B+bias), cols [N, ldc) zeroed (K-pad for next layer).
// MODE 1: dense-batch remap epilogue (no relu, no pad writes).
// AVEC 1: A loaded as unguarded float4 over Kp columns (requires lda%4==0, Kp<=lda,
//         Kp%16==0, pad cols of A zeroed). AVEC 0: scalar guarded loads (gk<Kreal).
template <int MODE, int AVEC>
__global__ __launch_bounds__(256) void k_gemm_tc(const float* __restrict__ A,
                                                 const float* __restrict__ B,
                                                 const float* __restrict__ bias,
                                                 const void* __restrict__ batch,
                                                 const int* __restrict__ starts,
                                                 float* __restrict__ C,
                                                 int M, int Kreal, int Kp, int N,
                                                 int lda, int ldc, int max_num) {
    __shared__ float As[16][132];
    __shared__ float Bs[16][136];
    int tid = threadIdx.x;
    int warp = tid >> 5, lane = tid & 31;
    int wm = warp >> 2, wn = warp & 3;       // wm: 2 x 64 rows, wn: 4 x 32 cols
    int gid = lane >> 2, t4 = lane & 3;
    int row0 = blockIdx.y * 128, col0 = blockIdx.x * 128;

    float acc[4][4][4];
    #pragma unroll
    for (int mt = 0; mt < 4; mt++)
        #pragma unroll
        for (int nt = 0; nt < 4; nt++)
            #pragma unroll
            for (int r = 0; r < 4; r++) acc[mt][nt][r] = 0.f;

    int ar_row = tid >> 1;                   // A-load: row per thread-pair
    int ak_base = (tid & 1) * 8;

    for (int kk = 0; kk < Kp; kk += 16) {
        {   // A tile 128x16
            int grow = row0 + ar_row;
            if (AVEC) {
                if (grow < M) {
                    const float4* ap = reinterpret_cast<const float4*>(
                        A + (size_t)grow * lda + kk + ak_base);
                    float4 v0 = ap[0], v1 = ap[1];
                    As[ak_base + 0][ar_row] = to_tf32(v0.x);
                    As[ak_base + 1][ar_row] = to_tf32(v0.y);
                    As[ak_base + 2][ar_row] = to_tf32(v0.z);
                    As[ak_base + 3][ar_row] = to_tf32(v0.w);
                    As[ak_base + 4][ar_row] = to_tf32(v1.x);
                    As[ak_base + 5][ar_row] = to_tf32(v1.y);
                    As[ak_base + 6][ar_row] = to_tf32(v1.z);
                    As[ak_base + 7][ar_row] = to_tf32(v1.w);
                } else {
                    #pragma unroll
                    for (int j = 0; j < 8; j++) As[ak_base + j][ar_row] = 0.f;
                }
            } else {
                #pragma unroll
                for (int j = 0; j < 8; j++) {
                    int gk = kk + ak_base + j;
                    float v = (grow < M && gk < Kreal) ? A[(size_t)grow * lda + gk] : 0.f;
                    As[ak_base + j][ar_row] = to_tf32(v);
                }
            }
        }
        #pragma unroll
        for (int rl = 0; rl < 8; rl++) {     // B tile 16x128
            int idx = tid + rl * 256;
            int br = idx >> 7, bc = idx & 127;
            int gk = kk + br, gc = col0 + bc;
            float v = (gk < Kreal && gc < N) ? B[(size_t)gk * N + gc] : 0.f;
            Bs[br][bc] = to_tf32(v);
        }
        __syncthreads();
        #pragma unroll
        for (int k8 = 0; k8 < 16; k8 += 8) {
            float bf[4][2];
            #pragma unroll
            for (int nt = 0; nt < 4; nt++) {
                int bc = wn * 32 + nt * 8 + gid;
                bf[nt][0] = Bs[k8 + t4][bc];
                bf[nt][1] = Bs[k8 + t4 + 4][bc];
            }
            #pragma unroll
            for (int mt = 0; mt < 4; mt++) {
                int ar = wm * 64 + mt * 16 + gid;
                float a0 = As[k8 + t4][ar];
                float a1 = As[k8 + t4][ar + 8];
                float a2 = As[k8 + t4 + 4][ar];
                float a3 = As[k8 + t4 + 4][ar + 8];
                #pragma unroll
                for (int nt = 0; nt < 4; nt++)
                    mma_tf32(acc[mt][nt][0], acc[mt][nt][1], acc[mt][nt][2], acc[mt][nt][3],
                             a0, a1, a2, a3, bf[nt][0], bf[nt][1]);
            }
        }
        __syncthreads();
    }

    int is64 = (MODE == 1) ? g_idx64 : 0;
    #pragma unroll
    for (int mt = 0; mt < 4; mt++) {
        #pragma unroll
        for (int half = 0; half < 2; half++) {
            int row = row0 + wm * 64 + mt * 16 + gid + half * 8;
            if (row >= M) continue;
            float* orow;
            if (MODE == 0) {
                orow = C + (size_t)row * ldc;
            } else {
                int bg = idx_at(batch, row, is64);
                int pos = row - starts[bg];
                if (pos >= max_num) continue;
                orow = C + ((size_t)bg * max_num + pos) * N;
            }
            #pragma unroll
            for (int nt = 0; nt < 4; nt++) {
                int col = col0 + wn * 32 + nt * 8 + t4 * 2;
                #pragma unroll
                for (int c = 0; c < 2; c++) {
                    int cc = col + c;
                    if (MODE == 0) {
                        if (cc < N) {
                            orow[cc] = fmaxf(acc[mt][nt][half * 2 + c] + bias[cc], 0.f);
                        } else if (cc < ldc) {
                            orow[cc] = 0.f;   // zero K-pad for the next layer
                        }
                    } else {
                        if (cc < N) orow[cc] = acc[mt][nt][half * 2 + c] + bias[cc];
                    }
                }
            }
        }
    }
}

// ---------------- host launcher ----------------
extern "C" void kernel_launch(void* const* d_in, const int* in_sizes, int n_in,
                              void* d_out, int out_size) {
    const float* x     = (const float*)d_in[0];
    const void*  ei    = d_in[1];
    const void*  batch = d_in[2];
    const float* W1 = (const float*)d_in[4];
    const float* b1 = (const float*)d_in[5];
    const float* W2 = (const float*)d_in[6];
    const float* b2 = (const float*)d_in[7];
    const float* W3 = (const float*)d_in[8];
    const float* b3 = (const float*)d_in[9];
    const float* Wf = (const float*)d_in[10];
    const float* bf = (const float*)d_in[11];
    float* out = (float*)d_out;

    int N  = in_sizes[2];
    int E  = in_sizes[1] / 2;
    int F0 = in_sizes[0] / N;        // 54
    int F2 = in_sizes[6] / F0;       // 108
    int F3 = in_sizes[8] / F2;       // 216
    int FO = in_sizes[10] / F3;      // 200
    int max_num = out_size / (NGRAPHS * FO);

    bool fast = (F0 == 54 && F2 == 108 && F3 == 216);

    float *p_h, *p_agg, *p_dinv;
    int *p_cnt, *p_rowptr, *p_cursor, *p_starts;
    int2* p_csr;
    cudaGetSymbolAddress((void**)&p_h, g_h);
    cudaGetSymbolAddress((void**)&p_agg, g_agg);
    cudaGetSymbolAddress((void**)&p_dinv, g_dinv);
    cudaGetSymbolAddress((void**)&p_cnt, g_cnt);
    cudaGetSymbolAddress((void**)&p_rowptr, g_rowptr);
    cudaGetSymbolAddress((void**)&p_cursor, g_cursor);
    cudaGetSymbolAddress((void**)&p_csr, g_csr);
    cudaGetSymbolAddress((void**)&p_starts, g_starts);

    const int T = 256;
    int nb_n = (N + T - 1) / T;
    int nb_e = (E + T - 1) / T;

    // fused: zero cnt + detect dtype + starts  (one extra block for the serial part)
    k_init<<<nb_n + 1, T>>>((const int*)ei, batch, p_cnt, p_starts, N);
    {
        dim3 zgrid(32, NGRAPHS);
        k_zero_tail<<<zgrid, T>>>((float4*)out, p_starts, max_num, FO, N);
    }
    k_count<<<nb_e, T>>>(ei, p_cnt, E, N);
    k_scan<<<1, 1024>>>(p_cnt, p_rowptr, p_cursor, p_dinv, N);
    k_fill<<<nb_e, T>>>(ei, p_dinv, p_cursor, p_csr, E, N);

    int mb = (N + 127) / 128;

    if (fast) {
        // strides: 64 / 112 / 224 floats (all %16==0), pads kept zero
        // ---- layer 1: agg(x:54) -> agg[64]; GEMM Kp=64 -> h[64] (zeros 54..63) ----
        k_agg_f2<27, 32><<<(N + 7) / 8, T>>>((const float2*)x, 27,
                                             p_rowptr, p_csr, p_dinv,
                                             (float2*)p_agg, N);
        {
            dim3 grid(1, mb);
            k_gemm_tc<0, 1><<<grid, T>>>(p_agg, W1, b1, nullptr, nullptr, p_h,
                                         N, 54, 64, 54, 64, 64, 0);
        }
        // ---- layer 2: agg(h[64]) f4 16 lanes GS=16 -> agg[64]; GEMM Kp=64 -> h[112] ----
        k_agg_f4<16, 16><<<(N + 15) / 16, T>>>((const float4*)p_h, 16,
                                               p_rowptr, p_csr, p_dinv,
                                               (float4*)p_agg, N);
        {
            dim3 grid(1, mb);
            k_gemm_tc<0, 1><<<grid, T>>>(p_agg, W2, b2, nullptr, nullptr, p_h,
                                         N, 54, 64, 108, 64, 112, 0);
        }
        // ---- layer 3: agg(h[112]) f4 28 lanes GS=32 -> agg[112]; GEMM Kp=112 -> h[224] ----
        k_agg_f4<28, 32><<<(N + 7) / 8, T>>>((const float4*)p_h, 28,
                                             p_rowptr, p_csr, p_dinv,
                                             (float4*)p_agg, N);
        {
            dim3 grid(2, mb);
            k_gemm_tc<0, 1><<<grid, T>>>(p_agg, W3, b3, nullptr, nullptr, p_h,
                                         N, 108, 112, 216, 112, 224, 0);
        }
        // ---- final: h[224] @ Wf + bf -> dense [64, max_num, 200], Kp=224 ----
        {
            dim3 grid(2, mb);
            k_gemm_tc<1, 1><<<grid, T>>>(p_h, Wf, bf, batch, p_starts, out,
                                         N, 216, 224, 200, 224, 200, max_num);
        }
    } else {
        // generic fallback: unpadded strides, guarded scalar A loads
        int K1p = ((F0 + 15) / 16) * 16;
        int K2p = ((F0 + 15) / 16) * 16;
        int K3p = ((F2 + 15) / 16) * 16;
        int KfP = ((F3 + 15) / 16) * 16;
        k_aggregate<<<N, ((F0 + 31) / 32) * 32>>>(x, p_rowptr, p_csr, p_dinv, p_agg, F0);
        {
            dim3 grid((F0 + 127) / 128, mb);
            k_gemm_tc<0, 0><<<grid, T>>>(p_agg, W1, b1, nullptr, nullptr, p_h,
                                         N, F0, K1p, F0, F0, F0, 0);
        }
        k_aggregate<<<N, ((F0 + 31) / 32) * 32>>>(p_h, p_rowptr, p_csr, p_dinv, p_agg, F0);
        {
            dim3 grid((F2 + 127) / 128, mb);
            k_gemm_tc<0, 0><<<grid, T>>>(p_agg, W2, b2, nullptr, nullptr, p_h,
                                         N, F0, K2p, F2, F0, F2, 0);
        }
        k_aggregate<<<N, ((F2 + 31) / 32) * 32>>>(p_h, p_rowptr, p_csr, p_dinv, p_agg, F2);
        {
            dim3 grid((F3 + 127) / 128, mb);
            k_gemm_tc<0, 0><<<grid, T>>>(p_agg, W3, b3, nullptr, nullptr, p_h,
                                         N, F2, K3p, F3, F2, F3, 0);
        }
        {
            dim3 grid((FO + 127) / 128, mb);
            k_gemm_tc<1, 0><<<grid, T>>>(p_h, Wf, bf, batch, p_starts, out,
                                         N, F3, KfP, FO, F3, FO, max_num);
        }
    }
}

// round 11
// speedup vs baseline: 1.5200x; 1.2945x over previous
#include <cuda_runtime.h>
#include <stdint.h>

#define MAXN 50000
#define MAXE 800000
#define MAXFP 224
#define NGRAPHS 64
#define SCAN_BLK 1024   // elements per scan1 block

// ---------------- scratch (static device globals; allocation-free) ----------------
__device__ __align__(16) float g_h[(size_t)MAXN * MAXFP];    // layer outputs (padded stride)
__device__ __align__(16) float g_agg[(size_t)MAXN * MAXFP];  // aggregated features (padded stride)
__device__ __align__(16) int g_cnt[MAXN];
__device__ int   g_rowptr[MAXN + 1];
__device__ int   g_cursor[MAXN];
__device__ __align__(16) int2 g_csr[MAXE];                   // packed {src, w-as-int}
__device__ float g_dinv[MAXN];
__device__ int   g_starts[NGRAPHS + 1];
__device__ int   g_bsum[256];
__device__ int   g_idx64;

__device__ __forceinline__ int idx_at(const void* p, long long i, int is64) {
    return is64 ? (int)((const long long*)p)[i] : ((const int*)p)[i];
}

// ---------------- fused init: zero cnt + detect idx dtype + starts ----------------
__global__ void k_init(const int* __restrict__ eiw, const void* __restrict__ batch,
                       int* cnt, int* starts, int n) {
    if (blockIdx.x == gridDim.x - 1) {
        __shared__ int s_is64;
        if (threadIdx.x == 0) {
            int is64 = 1;
            #pragma unroll 1
            for (int i = 1; i < 128; i += 2)
                if (eiw[i] != 0) { is64 = 0; break; }
            g_idx64 = is64;
            s_is64 = is64;
        }
        __syncthreads();
        int is64 = s_is64;
        int g = threadIdx.x;
        if (g < NGRAPHS) {
            int lo = 0, hi = n;
            while (lo < hi) {
                int mid = (lo + hi) >> 1;
                if (idx_at(batch, mid, is64) < g) lo = mid + 1; else hi = mid;
            }
            starts[g] = lo;
        }
    } else {
        int i = blockIdx.x * blockDim.x + threadIdx.x;
        if (i < n) cnt[i] = 0;
    }
}

// zero only invalid tail rows of the dense output
__global__ void k_zero_tail(float4* __restrict__ out4, const int* __restrict__ starts,
                            int max_num, int FO, int Ntot) {
    int g = blockIdx.y;
    int s0 = starts[g];
    int s1 = (g == NGRAPHS - 1) ? Ntot : starts[g + 1];
    int valid = s1 - s0; if (valid > max_num) valid = max_num;
    size_t rowq = (size_t)FO / 4;
    size_t base = ((size_t)g * max_num + valid) * rowq;
    size_t end  = ((size_t)(g + 1) * max_num) * rowq;
    float4 z = {0.f, 0.f, 0.f, 0.f};
    size_t i = base + blockIdx.x * blockDim.x + threadIdx.x;
    size_t stride = (size_t)gridDim.x * blockDim.x;
    for (; i < end; i += stride) out4[i] = z;
}

// ---------------- CSR build ----------------
__global__ void k_count(const void* __restrict__ ei, int* cnt, int E, int N) {
    int is64 = g_idx64;
    int i = blockIdx.x * blockDim.x + threadIdx.x;
    if (i < E) {
        int d = idx_at(ei, (long long)E + i, is64);
        if (d >= 0 && d < N) atomicAdd(&cnt[d], 1);
    }
}

// ---- hierarchical scan: 1) per-block scan, 2) block-sum scan, 3) apply ----
__global__ void k_scan1(const int* __restrict__ cnt, int* __restrict__ rowptr,
                        int* __restrict__ bsum, int n) {
    __shared__ int wsum[8];
    int tid = threadIdx.x;
    int lane = tid & 31, w = tid >> 5;
    int i0 = blockIdx.x * SCAN_BLK + tid * 4;
    int v[4];
    #pragma unroll
    for (int j = 0; j < 4; j++) v[j] = (i0 + j < n) ? cnt[i0 + j] : 0;
    int s = v[0] + v[1] + v[2] + v[3];
    int incl = s;
    #pragma unroll
    for (int off = 1; off < 32; off <<= 1) {
        int t = __shfl_up_sync(0xffffffffu, incl, off);
        if (lane >= off) incl += t;
    }
    if (lane == 31) wsum[w] = incl;
    __syncthreads();
    if (w == 0) {
        int ws = (lane < 8) ? wsum[lane] : 0;
        #pragma unroll
        for (int off = 1; off < 8; off <<= 1) {
            int t = __shfl_up_sync(0xffffffffu, ws, off);
            if (lane >= off) ws += t;
        }
        if (lane < 8) wsum[lane] = ws;
    }
    __syncthreads();
    int woff = (w > 0) ? wsum[w - 1] : 0;
    int run = woff + incl - s;   // exclusive prefix for this thread's first element
    #pragma unroll
    for (int j = 0; j < 4; j++) {
        if (i0 + j < n) rowptr[i0 + j] = run;
        run += v[j];
    }
    if (tid == 255) bsum[blockIdx.x] = woff + incl;  // block total
}

__global__ void k_scan2(int* __restrict__ bsum, int* __restrict__ rowptr_total, int nb) {
    __shared__ int s[256];
    int tid = threadIdx.x;
    int v = (tid < nb) ? bsum[tid] : 0;
    s[tid] = v;
    __syncthreads();
    for (int off = 1; off < 256; off <<= 1) {
        int t = (tid >= off) ? s[tid - off] : 0;
        __syncthreads();
        s[tid] += t;
        __syncthreads();
    }
    if (tid < nb) bsum[tid] = s[tid] - v;     // exclusive block offsets
    if (tid == nb - 1) *rowptr_total = s[tid];
}

__global__ void k_scan3(const int* __restrict__ cnt, const int* __restrict__ bsum,
                        int* __restrict__ rowptr, int* __restrict__ cursor,
                        float* __restrict__ dinv, int n) {
    int i = blockIdx.x * blockDim.x + threadIdx.x;
    if (i < n) {
        int r = rowptr[i] + bsum[i / SCAN_BLK];
        rowptr[i] = r;
        cursor[i] = r;
        dinv[i] = rsqrtf((float)cnt[i] + 1.0f);
    }
}

__global__ void k_fill(const void* __restrict__ ei,
                       const float* __restrict__ dinv, int* cursor,
                       int2* __restrict__ csr, int E, int N) {
    int is64 = g_idx64;
    int e = blockIdx.x * blockDim.x + threadIdx.x;
    if (e < E) {
        int s = idx_at(ei, e, is64);
        int d = idx_at(ei, (long long)E + e, is64);
        if (s >= 0 && s < N && d >= 0 && d < N) {
            int pos = atomicAdd(&cursor[d], 1);
            float w = dinv[s] * dinv[d];
            csr[pos] = make_int2(s, __float_as_int(w));
        }
    }
}

// ---------------- aggregation: float2 lanes (layer 1, unpadded external input) ----------------
template <int LANES, int OUT_S2>
__global__ __launch_bounds__(256) void k_agg_f2(const float2* __restrict__ h2,
                                                int in_s2,
                                                const int* __restrict__ rowptr,
                                                const int2* __restrict__ csr,
                                                const float* __restrict__ dinv,
                                                float2* __restrict__ agg2, int Nn) {
    const int GS = 32;
    int gid = threadIdx.x / GS;
    int lane = threadIdx.x % GS;
    int node = blockIdx.x * (256 / GS) + gid;
    if (node >= Nn) return;
    int e0 = rowptr[node], e1 = rowptr[node + 1];
    float ax = 0.f, ay = 0.f;
    bool act = lane < LANES;
    int t = e0;
    for (; t + 8 <= e1; t += 8) {
        int2 ew[8];
        #pragma unroll
        for (int u = 0; u < 8; u++) ew[u] = csr[t + u];
        if (act) {
            float2 v[8];
            #pragma unroll
            for (int u = 0; u < 8; u++) v[u] = h2[(size_t)ew[u].x * in_s2 + lane];
            #pragma unroll
            for (int u = 0; u < 8; u++) {
                float w = __int_as_float(ew[u].y);
                ax += w * v[u].x; ay += w * v[u].y;
            }
        }
    }
    for (; t < e1; t++) {
        int2 ew = csr[t];
        if (act) {
            float w = __int_as_float(ew.y);
            float2 v = h2[(size_t)ew.x * in_s2 + lane];
            ax += w * v.x; ay += w * v.y;
        }
    }
    float2 r = {0.f, 0.f};
    if (act) {
        float d = dinv[node];
        float2 self = h2[(size_t)node * in_s2 + lane];
        r.x = ax + d * d * self.x;
        r.y = ay + d * d * self.y;
    }
    agg2[(size_t)node * OUT_S2 + lane] = r;   // lanes >= LANES store zeros (pad)
}

// ---------------- aggregation: float4 lanes (padded intermediates, pads already zero) ----------------
template <int LANES4, int GS>
__global__ __launch_bounds__(256) void k_agg_f4(const float4* __restrict__ h4,
                                                int s4,
                                                const int* __restrict__ rowptr,
                                                const int2* __restrict__ csr,
                                                const float* __restrict__ dinv,
                                                float4* __restrict__ agg4, int Nn) {
    int gid = threadIdx.x / GS;
    int lane = threadIdx.x % GS;
    int node = blockIdx.x * (256 / GS) + gid;
    if (node >= Nn) return;
    int e0 = rowptr[node], e1 = rowptr[node + 1];
    float ax = 0.f, ay = 0.f, az = 0.f, aw = 0.f;
    bool act = lane < LANES4;
    int t = e0;
    for (; t + 8 <= e1; t += 8) {
        int2 ew[8];
        #pragma unroll
        for (int u = 0; u < 8; u++) ew[u] = csr[t + u];
        if (act) {
            float4 v[8];
            #pragma unroll
            for (int u = 0; u < 8; u++) v[u] = h4[(size_t)ew[u].x * s4 + lane];
            #pragma unroll
            for (int u = 0; u < 8; u++) {
                float w = __int_as_float(ew[u].y);
                ax += w * v[u].x; ay += w * v[u].y;
                az += w * v[u].z; aw += w * v[u].w;
            }
        }
    }
    for (; t < e1; t++) {
        int2 ew = csr[t];
        if (act) {
            float w = __int_as_float(ew.y);
            float4 v = h4[(size_t)ew.x * s4 + lane];
            ax += w * v.x; ay += w * v.y; az += w * v.z; aw += w * v.w;
        }
    }
    if (act) {
        float d = dinv[node];
        float d2 = d * d;
        float4 self = h4[(size_t)node * s4 + lane];
        float4 r;
        r.x = ax + d2 * self.x;
        r.y = ay + d2 * self.y;
        r.z = az + d2 * self.z;
        r.w = aw + d2 * self.w;
        agg4[(size_t)node * s4 + lane] = r;
    }
}

// generic fallback (any F, stride = F)
__global__ void k_aggregate(const float* __restrict__ h,
                            const int* __restrict__ rowptr,
                            const int2* __restrict__ csr,
                            const float* __restrict__ dinv,
                            float* __restrict__ agg, int F) {
    int i = blockIdx.x;
    int f = threadIdx.x;
    int e0 = rowptr[i], e1 = rowptr[i + 1];
    float acc = 0.f;
    if (f < F) {
        for (int t = e0; t < e1; t++) {
            int2 ew = csr[t];
            acc += h[(size_t)ew.x * F + f] * __int_as_float(ew.y);
        }
        float d = dinv[i];
        agg[(size_t)i * F + f] = acc + d * d * h[(size_t)i * F + f];
    }
}

// ---------------- tf32 tensor-core GEMM, BM=128 BN=128 BK=16 ----------------
__device__ __forceinline__ float to_tf32(float x) {
    float y;
    asm("cvt.rna.tf32.f32 %0, %1;" : "=f"(y) : "f"(x));
    return y;
}

__device__ __forceinline__ void mma_tf32(float& d0, float& d1, float& d2, float& d3,
                                         float a0, float a1, float a2, float a3,
                                         float b0, float b1) {
    asm("mma.sync.aligned.m16n8k8.row.col.f32.tf32.tf32.f32 "
        "{%0,%1,%2,%3},{%4,%5,%6,%7},{%8,%9},{%0,%1,%2,%3};"
        : "+f"(d0), "+f"(d1), "+f"(d2), "+f"(d3)
        : "r"(__float_as_uint(a0)), "r"(__float_as_uint(a1)),
          "r"(__float_as_uint(a2)), "r"(__float_as_uint(a3)),
          "r"(__float_as_uint(b0)), "r"(__float_as_uint(b1)));
}

// MODE 0: C = relu(A@B+bias), cols [N, ldc) zeroed. MODE 1: dense-batch remap.
// AVEC 1: unguarded float4 A loads over Kp (pads zeroed). AVEC 0: guarded scalar.
template <int MODE, int AVEC>
__global__ __launch_bounds__(256) void k_gemm_tc(const float* __restrict__ A,
                                                 const float* __restrict__ B,
                                                 const float* __restrict__ bias,
                                                 const void* __restrict__ batch,
                                                 const int* __restrict__ starts,
                                                 float* __restrict__ C,
                                                 int M, int Kreal, int Kp, int N,
                                                 int lda, int ldc, int max_num) {
    __shared__ float As[16][132];
    __shared__ float Bs[16][136];
    int tid = threadIdx.x;
    int warp = tid >> 5, lane = tid & 31;
    int wm = warp >> 2, wn = warp & 3;
    int gid = lane >> 2, t4 = lane & 3;
    int row0 = blockIdx.y * 128, col0 = blockIdx.x * 128;

    float acc[4][4][4];
    #pragma unroll
    for (int mt = 0; mt < 4; mt++)
        #pragma unroll
        for (int nt = 0; nt < 4; nt++)
            #pragma unroll
            for (int r = 0; r < 4; r++) acc[mt][nt][r] = 0.f;

    int ar_row = tid >> 1;
    int ak_base = (tid & 1) * 8;

    for (int kk = 0; kk < Kp; kk += 16) {
        {   // A tile 128x16
            int grow = row0 + ar_row;
            if (AVEC) {
                if (grow < M) {
                    const float4* ap = reinterpret_cast<const float4*>(
                        A + (size_t)grow * lda + kk + ak_base);
                    float4 v0 = ap[0], v1 = ap[1];
                    As[ak_base + 0][ar_row] = to_tf32(v0.x);
                    As[ak_base + 1][ar_row] = to_tf32(v0.y);
                    As[ak_base + 2][ar_row] = to_tf32(v0.z);
                    As[ak_base + 3][ar_row] = to_tf32(v0.w);
                    As[ak_base + 4][ar_row] = to_tf32(v1.x);
                    As[ak_base + 5][ar_row] = to_tf32(v1.y);
                    As[ak_base + 6][ar_row] = to_tf32(v1.z);
                    As[ak_base + 7][ar_row] = to_tf32(v1.w);
                } else {
                    #pragma unroll
                    for (int j = 0; j < 8; j++) As[ak_base + j][ar_row] = 0.f;
                }
            } else {
                #pragma unroll
                for (int j = 0; j < 8; j++) {
                    int gk = kk + ak_base + j;
                    float v = (grow < M && gk < Kreal) ? A[(size_t)grow * lda + gk] : 0.f;
                    As[ak_base + j][ar_row] = to_tf32(v);
                }
            }
        }
        #pragma unroll
        for (int rl = 0; rl < 8; rl++) {     // B tile 16x128
            int idx = tid + rl * 256;
            int br = idx >> 7, bc = idx & 127;
            int gk = kk + br, gc = col0 + bc;
            float v = (gk < Kreal && gc < N) ? B[(size_t)gk * N + gc] : 0.f;
            Bs[br][bc] = to_tf32(v);
        }
        __syncthreads();
        #pragma unroll
        for (int k8 = 0; k8 < 16; k8 += 8) {
            float bf[4][2];
            #pragma unroll
            for (int nt = 0; nt < 4; nt++) {
                int bc = wn * 32 + nt * 8 + gid;
                bf[nt][0] = Bs[k8 + t4][bc];
                bf[nt][1] = Bs[k8 + t4 + 4][bc];
            }
            #pragma unroll
            for (int mt = 0; mt < 4; mt++) {
                int ar = wm * 64 + mt * 16 + gid;
                float a0 = As[k8 + t4][ar];
                float a1 = As[k8 + t4][ar + 8];
                float a2 = As[k8 + t4 + 4][ar];
                float a3 = As[k8 + t4 + 4][ar + 8];
                #pragma unroll
                for (int nt = 0; nt < 4; nt++)
                    mma_tf32(acc[mt][nt][0], acc[mt][nt][1], acc[mt][nt][2], acc[mt][nt][3],
                             a0, a1, a2, a3, bf[nt][0], bf[nt][1]);
            }
        }
        __syncthreads();
    }

    int is64 = (MODE == 1) ? g_idx64 : 0;
    #pragma unroll
    for (int mt = 0; mt < 4; mt++) {
        #pragma unroll
        for (int half = 0; half < 2; half++) {
            int row = row0 + wm * 64 + mt * 16 + gid + half * 8;
            if (row >= M) continue;
            float* orow;
            if (MODE == 0) {
                orow = C + (size_t)row * ldc;
            } else {
                int bg = idx_at(batch, row, is64);
                int pos = row - starts[bg];
                if (pos >= max_num) continue;
                orow = C + ((size_t)bg * max_num + pos) * N;
            }
            #pragma unroll
            for (int nt = 0; nt < 4; nt++) {
                int col = col0 + wn * 32 + nt * 8 + t4 * 2;
                #pragma unroll
                for (int c = 0; c < 2; c++) {
                    int cc = col + c;
                    if (MODE == 0) {
                        if (cc < N) {
                            orow[cc] = fmaxf(acc[mt][nt][half * 2 + c] + bias[cc], 0.f);
                        } else if (cc < ldc) {
                            orow[cc] = 0.f;
                        }
                    } else {
                        if (cc < N) orow[cc] = acc[mt][nt][half * 2 + c] + bias[cc];
                    }
                }
            }
        }
    }
}

// ---------------- host launcher ----------------
extern "C" void kernel_launch(void* const* d_in, const int* in_sizes, int n_in,
                              void* d_out, int out_size) {
    const float* x     = (const float*)d_in[0];
    const void*  ei    = d_in[1];
    const void*  batch = d_in[2];
    const float* W1 = (const float*)d_in[4];
    const float* b1 = (const float*)d_in[5];
    const float* W2 = (const float*)d_in[6];
    const float* b2 = (const float*)d_in[7];
    const float* W3 = (const float*)d_in[8];
    const float* b3 = (const float*)d_in[9];
    const float* Wf = (const float*)d_in[10];
    const float* bf = (const float*)d_in[11];
    float* out = (float*)d_out;

    int N  = in_sizes[2];
    int E  = in_sizes[1] / 2;
    int F0 = in_sizes[0] / N;        // 54
    int F2 = in_sizes[6] / F0;       // 108
    int F3 = in_sizes[8] / F2;       // 216
    int FO = in_sizes[10] / F3;      // 200
    int max_num = out_size / (NGRAPHS * FO);

    bool fast = (F0 == 54 && F2 == 108 && F3 == 216);

    float *p_h, *p_agg, *p_dinv;
    int *p_cnt, *p_rowptr, *p_cursor, *p_starts, *p_bsum;
    int2* p_csr;
    cudaGetSymbolAddress((void**)&p_h, g_h);
    cudaGetSymbolAddress((void**)&p_agg, g_agg);
    cudaGetSymbolAddress((void**)&p_dinv, g_dinv);
    cudaGetSymbolAddress((void**)&p_cnt, g_cnt);
    cudaGetSymbolAddress((void**)&p_rowptr, g_rowptr);
    cudaGetSymbolAddress((void**)&p_cursor, g_cursor);
    cudaGetSymbolAddress((void**)&p_csr, g_csr);
    cudaGetSymbolAddress((void**)&p_starts, g_starts);
    cudaGetSymbolAddress((void**)&p_bsum, g_bsum);

    const int T = 256;
    int nb_n = (N + T - 1) / T;
    int nb_e = (E + T - 1) / T;
    int nb_scan = (N + SCAN_BLK - 1) / SCAN_BLK;

    // fused: zero cnt + detect dtype + starts
    k_init<<<nb_n + 1, T>>>((const int*)ei, batch, p_cnt, p_starts, N);
    {
        dim3 zgrid(32, NGRAPHS);
        k_zero_tail<<<zgrid, T>>>((float4*)out, p_starts, max_num, FO, N);
    }
    k_count<<<nb_e, T>>>(ei, p_cnt, E, N);
    // hierarchical scan (rowptr exclusive; cursor copy; dinv)
    k_scan1<<<nb_scan, T>>>(p_cnt, p_rowptr, p_bsum, N);
    k_scan2<<<1, T>>>(p_bsum, p_rowptr + N, nb_scan);
    k_scan3<<<nb_n, T>>>(p_cnt, p_bsum, p_rowptr, p_cursor, p_dinv, N);
    k_fill<<<nb_e, T>>>(ei, p_dinv, p_cursor, p_csr, E, N);

    int mb = (N + 127) / 128;

    if (fast) {
        // strides: 64 / 112 / 224 floats (all %16==0), pads kept zero
        k_agg_f2<27, 32><<<(N + 7) / 8, T>>>((const float2*)x, 27,
                                             p_rowptr, p_csr, p_dinv,
                                             (float2*)p_agg, N);
        {
            dim3 grid(1, mb);
            k_gemm_tc<0, 1><<<grid, T>>>(p_agg, W1, b1, nullptr, nullptr, p_h,
                                         N, 54, 64, 54, 64, 64, 0);
        }
        k_agg_f4<16, 16><<<(N + 15) / 16, T>>>((const float4*)p_h, 16,
                                               p_rowptr, p_csr, p_dinv,
                                               (float4*)p_agg, N);
        {
            dim3 grid(1, mb);
            k_gemm_tc<0, 1><<<grid, T>>>(p_agg, W2, b2, nullptr, nullptr, p_h,
                                         N, 54, 64, 108, 64, 112, 0);
        }
        k_agg_f4<28, 32><<<(N + 7) / 8, T>>>((const float4*)p_h, 28,
                                             p_rowptr, p_csr, p_dinv,
                                             (float4*)p_agg, N);
        {
            dim3 grid(2, mb);
            k_gemm_tc<0, 1><<<grid, T>>>(p_agg, W3, b3, nullptr, nullptr, p_h,
                                         N, 108, 112, 216, 112, 224, 0);
        }
        {
            dim3 grid(2, mb);
            k_gemm_tc<1, 1><<<grid, T>>>(p_h, Wf, bf, batch, p_starts, out,
                                         N, 216, 224, 200, 224, 200, max_num);
        }
    } else {
        int K1p = ((F0 + 15) / 16) * 16;
        int K2p = ((F0 + 15) / 16) * 16;
        int K3p = ((F2 + 15) / 16) * 16;
        int KfP = ((F3 + 15) / 16) * 16;
        k_aggregate<<<N, ((F0 + 31) / 32) * 32>>>(x, p_rowptr, p_csr, p_dinv, p_agg, F0);
        {
            dim3 grid((F0 + 127) / 128, mb);
            k_gemm_tc<0, 0><<<grid, T>>>(p_agg, W1, b1, nullptr, nullptr, p_h,
                                         N, F0, K1p, F0, F0, F0, 0);
        }
        k_aggregate<<<N, ((F0 + 31) / 32) * 32>>>(p_h, p_rowptr, p_csr, p_dinv, p_agg, F0);
        {
            dim3 grid((F2 + 127) / 128, mb);
            k_gemm_tc<0, 0><<<grid, T>>>(p_agg, W2, b2, nullptr, nullptr, p_h,
                                         N, F0, K2p, F2, F0, F2, 0);
        }
        k_aggregate<<<N, ((F2 + 31) / 32) * 32>>>(p_h, p_rowptr, p_csr, p_dinv, p_agg, F2);
        {
            dim3 grid((F3 + 127) / 128, mb);
            k_gemm_tc<0, 0><<<grid, T>>>(p_agg, W3, b3, nullptr, nullptr, p_h,
                                         N, F2, K3p, F3, F2, F3, 0);
        }
        {
            dim3 grid((FO + 127) / 128, mb);
            k_gemm_tc<1, 0><<<grid, T>>>(p_h, Wf, bf, batch, p_starts, out,
                                         N, F3, KfP, FO, F3, FO, max_num);
        }
    }
}

// round 14
// speedup vs baseline: 1.7227x; 1.1333x over previous
#include <cuda_runtime.h>
#include <stdint.h>

#define MAXN 50000
#define MAXE 800000
#define MAXFP 224
#define NGRAPHS 64
#define SCAN_BLK 1024

// ---------------- scratch (static device globals; allocation-free) ----------------
__device__ __align__(16) float g_h[(size_t)MAXN * MAXFP];
__device__ __align__(16) float g_agg[(size_t)MAXN * MAXFP];
__device__ __align__(16) int g_cnt[MAXN];
__device__ int   g_rowptr[MAXN + 1];
__device__ int   g_cursor[MAXN];
__device__ __align__(16) int2 g_csr[MAXE];
__device__ float g_dinv[MAXN];
__device__ int   g_starts[NGRAPHS + 1];
__device__ int   g_bsum[256];
__device__ int   g_idx64;

__device__ __forceinline__ int idx_at(const void* p, long long i, int is64) {
    return is64 ? (int)((const long long*)p)[i] : ((const int*)p)[i];
}

// ---------------- fused init: zero cnt + detect idx dtype + starts ----------------
__global__ void k_init(const int* __restrict__ eiw, const void* __restrict__ batch,
                       int* cnt, int* starts, int n) {
    if (blockIdx.x == gridDim.x - 1) {
        __shared__ int s_is64;
        if (threadIdx.x == 0) {
            int is64 = 1;
            #pragma unroll 1
            for (int i = 1; i < 128; i += 2)
                if (eiw[i] != 0) { is64 = 0; break; }
            g_idx64 = is64;
            s_is64 = is64;
        }
        __syncthreads();
        int is64 = s_is64;
        int g = threadIdx.x;
        if (g < NGRAPHS) {
            int lo = 0, hi = n;
            while (lo < hi) {
                int mid = (lo + hi) >> 1;
                if (idx_at(batch, mid, is64) < g) lo = mid + 1; else hi = mid;
            }
            starts[g] = lo;
        }
    } else {
        int i = blockIdx.x * blockDim.x + threadIdx.x;
        if (i < n) cnt[i] = 0;
    }
}

__global__ void k_zero_tail(float4* __restrict__ out4, const int* __restrict__ starts,
                            int max_num, int FO, int Ntot) {
    int g = blockIdx.y;
    int s0 = starts[g];
    int s1 = (g == NGRAPHS - 1) ? Ntot : starts[g + 1];
    int valid = s1 - s0; if (valid > max_num) valid = max_num;
    size_t rowq = (size_t)FO / 4;
    size_t base = ((size_t)g * max_num + valid) * rowq;
    size_t end  = ((size_t)(g + 1) * max_num) * rowq;
    float4 z = {0.f, 0.f, 0.f, 0.f};
    size_t i = base + blockIdx.x * blockDim.x + threadIdx.x;
    size_t stride = (size_t)gridDim.x * blockDim.x;
    for (; i < end; i += stride) out4[i] = z;
}

// ---------------- CSR build ----------------
__global__ void k_count(const void* __restrict__ ei, int* cnt, int E, int N) {
    int is64 = g_idx64;
    int i = blockIdx.x * blockDim.x + threadIdx.x;
    if (i < E) {
        int d = idx_at(ei, (long long)E + i, is64);
        if (d >= 0 && d < N) atomicAdd(&cnt[d], 1);
    }
}

__global__ void k_scan1(const int* __restrict__ cnt, int* __restrict__ rowptr,
                        int* __restrict__ bsum, int n) {
    __shared__ int wsum[8];
    int tid = threadIdx.x;
    int lane = tid & 31, w = tid >> 5;
    int i0 = blockIdx.x * SCAN_BLK + tid * 4;
    int v[4];
    #pragma unroll
    for (int j = 0; j < 4; j++) v[j] = (i0 + j < n) ? cnt[i0 + j] : 0;
    int s = v[0] + v[1] + v[2] + v[3];
    int incl = s;
    #pragma unroll
    for (int off = 1; off < 32; off <<= 1) {
        int t = __shfl_up_sync(0xffffffffu, incl, off);
        if (lane >= off) incl += t;
    }
    if (lane == 31) wsum[w] = incl;
    __syncthreads();
    if (w == 0) {
        int ws = (lane < 8) ? wsum[lane] : 0;
        #pragma unroll
        for (int off = 1; off < 8; off <<= 1) {
            int t = __shfl_up_sync(0xffffffffu, ws, off);
            if (lane >= off) ws += t;
        }
        if (lane < 8) wsum[lane] = ws;
    }
    __syncthreads();
    int woff = (w > 0) ? wsum[w - 1] : 0;
    int run = woff + incl - s;
    #pragma unroll
    for (int j = 0; j < 4; j++) {
        if (i0 + j < n) rowptr[i0 + j] = run;
        run += v[j];
    }
    if (tid == 255) bsum[blockIdx.x] = woff + incl;
}

__global__ void k_scan2(int* __restrict__ bsum, int* __restrict__ rowptr_total, int nb) {
    __shared__ int s[256];
    int tid = threadIdx.x;
    int v = (tid < nb) ? bsum[tid] : 0;
    s[tid] = v;
    __syncthreads();
    for (int off = 1; off < 256; off <<= 1) {
        int t = (tid >= off) ? s[tid - off] : 0;
        __syncthreads();
        s[tid] += t;
        __syncthreads();
    }
    if (tid < nb) bsum[tid] = s[tid] - v;
    if (tid == nb - 1) *rowptr_total = s[tid];
}

__global__ void k_scan3(const int* __restrict__ cnt, const int* __restrict__ bsum,
                        int* __restrict__ rowptr, int* __restrict__ cursor,
                        float* __restrict__ dinv, int n) {
    int i = blockIdx.x * blockDim.x + threadIdx.x;
    if (i < n) {
        int r = rowptr[i] + bsum[i / SCAN_BLK];
        rowptr[i] = r;
        cursor[i] = r;
        dinv[i] = rsqrtf((float)cnt[i] + 1.0f);
    }
}

__global__ void k_fill(const void* __restrict__ ei,
                       const float* __restrict__ dinv, int* cursor,
                       int2* __restrict__ csr, int E, int N) {
    int is64 = g_idx64;
    int e = blockIdx.x * blockDim.x + threadIdx.x;
    if (e < E) {
        int s = idx_at(ei, e, is64);
        int d = idx_at(ei, (long long)E + e, is64);
        if (s >= 0 && s < N && d >= 0 && d < N) {
            int pos = atomicAdd(&cursor[d], 1);
            float w = dinv[s] * dinv[d];
            csr[pos] = make_int2(s, __float_as_int(w));
        }
    }
}

// ---------------- aggregation: float2 lanes (layer 1) ----------------
template <int LANES, int OUT_S2>
__global__ __launch_bounds__(256) void k_agg_f2(const float2* __restrict__ h2,
                                                int in_s2,
                                                const int* __restrict__ rowptr,
                                                const int2* __restrict__ csr,
                                                const float* __restrict__ dinv,
                                                float2* __restrict__ agg2, int Nn) {
    const int GS = 32;
    int gid = threadIdx.x / GS;
    int lane = threadIdx.x % GS;
    int node = blockIdx.x * (256 / GS) + gid;
    if (node >= Nn) return;
    int e0 = rowptr[node], e1 = rowptr[node + 1];
    float ax = 0.f, ay = 0.f;
    bool act = lane < LANES;
    int t = e0;
    for (; t + 8 <= e1; t += 8) {
        int2 ew[8];
        #pragma unroll
        for (int u = 0; u < 8; u++) ew[u] = csr[t + u];
        if (act) {
            float2 v[8];
            #pragma unroll
            for (int u = 0; u < 8; u++) v[u] = h2[(size_t)ew[u].x * in_s2 + lane];
            #pragma unroll
            for (int u = 0; u < 8; u++) {
                float w = __int_as_float(ew[u].y);
                ax += w * v[u].x; ay += w * v[u].y;
            }
        }
    }
    for (; t < e1; t++) {
        int2 ew = csr[t];
        if (act) {
            float w = __int_as_float(ew.y);
            float2 v = h2[(size_t)ew.x * in_s2 + lane];
            ax += w * v.x; ay += w * v.y;
        }
    }
    float2 r = {0.f, 0.f};
    if (act) {
        float d = dinv[node];
        float2 self = h2[(size_t)node * in_s2 + lane];
        r.x = ax + d * d * self.x;
        r.y = ay + d * d * self.y;
    }
    agg2[(size_t)node * OUT_S2 + lane] = r;
}

// ---------------- aggregation: float4 lanes ----------------
template <int LANES4, int GS>
__global__ __launch_bounds__(256) void k_agg_f4(const float4* __restrict__ h4,
                                                int s4,
                                                const int* __restrict__ rowptr,
                                                const int2* __restrict__ csr,
                                                const float* __restrict__ dinv,
                                                float4* __restrict__ agg4, int Nn) {
    int gid = threadIdx.x / GS;
    int lane = threadIdx.x % GS;
    int node = blockIdx.x * (256 / GS) + gid;
    if (node >= Nn) return;
    int e0 = rowptr[node], e1 = rowptr[node + 1];
    float ax = 0.f, ay = 0.f, az = 0.f, aw = 0.f;
    bool act = lane < LANES4;
    int t = e0;
    for (; t + 8 <= e1; t += 8) {
        int2 ew[8];
        #pragma unroll
        for (int u = 0; u < 8; u++) ew[u] = csr[t + u];
        if (act) {
            float4 v[8];
            #pragma unroll
            for (int u = 0; u < 8; u++) v[u] = h4[(size_t)ew[u].x * s4 + lane];
            #pragma unroll
            for (int u = 0; u < 8; u++) {
                float w = __int_as_float(ew[u].y);
                ax += w * v[u].x; ay += w * v[u].y;
                az += w * v[u].z; aw += w * v[u].w;
            }
        }
    }
    for (; t < e1; t++) {
        int2 ew = csr[t];
        if (act) {
            float w = __int_as_float(ew.y);
            float4 v = h4[(size_t)ew.x * s4 + lane];
            ax += w * v.x; ay += w * v.y; az += w * v.z; aw += w * v.w;
        }
    }
    if (act) {
        float d = dinv[node];
        float d2 = d * d;
        float4 self = h4[(size_t)node * s4 + lane];
        float4 r;
        r.x = ax + d2 * self.x;
        r.y = ay + d2 * self.y;
        r.z = az + d2 * self.z;
        r.w = aw + d2 * self.w;
        agg4[(size_t)node * s4 + lane] = r;
    }
}

// generic fallback agg
__global__ void k_aggregate(const float* __restrict__ h,
                            const int* __restrict__ rowptr,
                            const int2* __restrict__ csr,
                            const float* __restrict__ dinv,
                            float* __restrict__ agg, int F) {
    int i = blockIdx.x;
    int f = threadIdx.x;
    int e0 = rowptr[i], e1 = rowptr[i + 1];
    float acc = 0.f;
    if (f < F) {
        for (int t = e0; t < e1; t++) {
            int2 ew = csr[t];
            acc += h[(size_t)ew.x * F + f] * __int_as_float(ew.y);
        }
        float d = dinv[i];
        agg[(size_t)i * F + f] = acc + d * d * h[(size_t)i * F + f];
    }
}

// ---------------- tf32 MMA helpers ----------------
__device__ __forceinline__ float to_tf32(float x) {
    float y;
    asm("cvt.rna.tf32.f32 %0, %1;" : "=f"(y) : "f"(x));
    return y;
}

__device__ __forceinline__ void mma_tf32(float& d0, float& d1, float& d2, float& d3,
                                         float a0, float a1, float a2, float a3,
                                         float b0, float b1) {
    asm("mma.sync.aligned.m16n8k8.row.col.f32.tf32.tf32.f32 "
        "{%0,%1,%2,%3},{%4,%5,%6,%7},{%8,%9},{%0,%1,%2,%3};"
        : "+f"(d0), "+f"(d1), "+f"(d2), "+f"(d3)
        : "r"(__float_as_uint(a0)), "r"(__float_as_uint(a1)),
          "r"(__float_as_uint(a2)), "r"(__float_as_uint(a3)),
          "r"(__float_as_uint(b0)), "r"(__float_as_uint(b1)));
}

__device__ __forceinline__ void cp_async16(uint32_t dst, const void* src, int src_bytes) {
    asm volatile("cp.async.ca.shared.global [%0], [%1], 16, %2;\n"
                 :: "r"(dst), "l"(src), "r"(src_bytes));
}
// 4-byte cp.async: only 4B alignment required (safe for arbitrary float row strides)
__device__ __forceinline__ void cp_async4(uint32_t dst, const void* src, int src_bytes) {
    asm volatile("cp.async.ca.shared.global [%0], [%1], 4, %2;\n"
                 :: "r"(dst), "l"(src), "r"(src_bytes));
}

// ---------------- cp.async double-buffered tf32 GEMM, BM=128 BN=128 BK=16 ----------------
// A: 16B cp.async (scratch strides are 16B multiples). B: 4B cp.async (external
// weights may have rows like 54 floats = 216B, NOT 16B aligned -> 16B cp illegal).
template <int MODE>
__global__ __launch_bounds__(256) void k_gemm_ca(const float* __restrict__ A,
                                                 const float* __restrict__ B,
                                                 const float* __restrict__ bias,
                                                 const void* __restrict__ batch,
                                                 const int* __restrict__ starts,
                                                 float* __restrict__ C,
                                                 int M, int Kreal, int Kp, int N,
                                                 int lda, int ldc, int max_num) {
    const int AP = 20;   // A smem row pad (floats)
    const int BP = 136;  // B smem row pad
    __shared__ float As[2][128 * AP];
    __shared__ float Bs[2][16 * BP];
    int tid = threadIdx.x;
    int warp = tid >> 5, lane = tid & 31;
    int wm = warp >> 2, wn = warp & 3;
    int gid = lane >> 2, t4 = lane & 3;
    int row0 = blockIdx.y * 128, col0 = blockIdx.x * 128;

    uint32_t asb[2], bsb[2];
    asb[0] = (uint32_t)__cvta_generic_to_shared(&As[0][0]);
    asb[1] = (uint32_t)__cvta_generic_to_shared(&As[1][0]);
    bsb[0] = (uint32_t)__cvta_generic_to_shared(&Bs[0][0]);
    bsb[1] = (uint32_t)__cvta_generic_to_shared(&Bs[1][0]);

    float acc[4][4][4];
    #pragma unroll
    for (int mt = 0; mt < 4; mt++)
        #pragma unroll
        for (int nt = 0; nt < 4; nt++)
            #pragma unroll
            for (int r = 0; r < 4; r++) acc[mt][nt][r] = 0.f;

    int nk = Kp >> 4;

    auto issue = [&](int t, int buf) {
        int kk = t << 4;
        // A tile: 128 rows x 16 floats = 512 x 16B chunks, 2 per thread
        #pragma unroll
        for (int c = 0; c < 2; c++) {
            int chunk = tid + c * 256;
            int row = chunk >> 2, seg = chunk & 3;
            int grow = row0 + row;
            bool ok = grow < M;
            const float* src = ok ? (A + (size_t)grow * lda + kk + seg * 4) : A;
            cp_async16(asb[buf] + (uint32_t)(row * AP + seg * 4) * 4, src, ok ? 16 : 0);
        }
        // B tile: 16 rows x 128 floats = 2048 x 4B words, 8 per thread
        #pragma unroll
        for (int c = 0; c < 8; c++) {
            int word = tid + c * 256;
            int brow = word >> 7, bcol = word & 127;
            int gk = kk + brow, gc = col0 + bcol;
            bool ok = (gk < Kreal) && (gc < N);
            const float* src = ok ? (B + (size_t)gk * N + gc) : B;
            cp_async4(bsb[buf] + (uint32_t)(brow * BP + bcol) * 4, src, ok ? 4 : 0);
        }
        asm volatile("cp.async.commit_group;\n");
    };

    issue(0, 0);
    for (int t = 0; t < nk; t++) {
        int cur = t & 1;
        asm volatile("cp.async.wait_group 0;\n");
        __syncthreads();
        if (t + 1 < nk) issue(t + 1, cur ^ 1);

        const float* as = &As[cur][0];
        const float* bs = &Bs[cur][0];
        #pragma unroll
        for (int k8 = 0; k8 < 16; k8 += 8) {
            float bf[4][2];
            #pragma unroll
            for (int nt = 0; nt < 4; nt++) {
                int bc = wn * 32 + nt * 8 + gid;
                bf[nt][0] = to_tf32(bs[(k8 + t4) * BP + bc]);
                bf[nt][1] = to_tf32(bs[(k8 + t4 + 4) * BP + bc]);
            }
            #pragma unroll
            for (int mt = 0; mt < 4; mt++) {
                int ar = wm * 64 + mt * 16 + gid;
                float a0 = to_tf32(as[ar * AP + k8 + t4]);
                float a1 = to_tf32(as[(ar + 8) * AP + k8 + t4]);
                float a2 = to_tf32(as[ar * AP + k8 + t4 + 4]);
                float a3 = to_tf32(as[(ar + 8) * AP + k8 + t4 + 4]);
                #pragma unroll
                for (int nt = 0; nt < 4; nt++)
                    mma_tf32(acc[mt][nt][0], acc[mt][nt][1], acc[mt][nt][2], acc[mt][nt][3],
                             a0, a1, a2, a3, bf[nt][0], bf[nt][1]);
            }
        }
        __syncthreads();
    }

    int is64 = (MODE == 1) ? g_idx64 : 0;
    #pragma unroll
    for (int mt = 0; mt < 4; mt++) {
        #pragma unroll
        for (int half = 0; half < 2; half++) {
            int row = row0 + wm * 64 + mt * 16 + gid + half * 8;
            if (row >= M) continue;
            float* orow;
            if (MODE == 0) {
                orow = C + (size_t)row * ldc;
            } else {
                int bg = idx_at(batch, row, is64);
                int pos = row - starts[bg];
                if (pos >= max_num) continue;
                orow = C + ((size_t)bg * max_num + pos) * N;
            }
            #pragma unroll
            for (int nt = 0; nt < 4; nt++) {
                int col = col0 + wn * 32 + nt * 8 + t4 * 2;
                #pragma unroll
                for (int c = 0; c < 2; c++) {
                    int cc = col + c;
                    if (MODE == 0) {
                        if (cc < N) {
                            orow[cc] = fmaxf(acc[mt][nt][half * 2 + c] + bias[cc], 0.f);
                        } else if (cc < ldc) {
                            orow[cc] = 0.f;
                        }
                    } else {
                        if (cc < N) orow[cc] = acc[mt][nt][half * 2 + c] + bias[cc];
                    }
                }
            }
        }
    }
}

// ---------------- legacy GEMM (generic fallback) ----------------
template <int MODE>
__global__ __launch_bounds__(256) void k_gemm_tc(const float* __restrict__ A,
                                                 const float* __restrict__ B,
                                                 const float* __restrict__ bias,
                                                 const void* __restrict__ batch,
                                                 const int* __restrict__ starts,
                                                 float* __restrict__ C,
                                                 int M, int Kreal, int Kp, int N,
                                                 int lda, int ldc, int max_num) {
    __shared__ float As[16][132];
    __shared__ float Bs[16][136];
    int tid = threadIdx.x;
    int warp = tid >> 5, lane = tid & 31;
    int wm = warp >> 2, wn = warp & 3;
    int gid = lane >> 2, t4 = lane & 3;
    int row0 = blockIdx.y * 128, col0 = blockIdx.x * 128;

    float acc[4][4][4];
    #pragma unroll
    for (int mt = 0; mt < 4; mt++)
        #pragma unroll
        for (int nt = 0; nt < 4; nt++)
            #pragma unroll
            for (int r = 0; r < 4; r++) acc[mt][nt][r] = 0.f;

    int ar_row = tid >> 1;
    int ak_base = (tid & 1) * 8;

    for (int kk = 0; kk < Kp; kk += 16) {
        {
            int grow = row0 + ar_row;
            #pragma unroll
            for (int j = 0; j < 8; j++) {
                int gk = kk + ak_base + j;
                float v = (grow < M && gk < Kreal) ? A[(size_t)grow * lda + gk] : 0.f;
                As[ak_base + j][ar_row] = to_tf32(v);
            }
        }
        #pragma unroll
        for (int rl = 0; rl < 8; rl++) {
            int idx = tid + rl * 256;
            int br = idx >> 7, bc = idx & 127;
            int gk = kk + br, gc = col0 + bc;
            float v = (gk < Kreal && gc < N) ? B[(size_t)gk * N + gc] : 0.f;
            Bs[br][bc] = to_tf32(v);
        }
        __syncthreads();
        #pragma unroll
        for (int k8 = 0; k8 < 16; k8 += 8) {
            float bf[4][2];
            #pragma unroll
            for (int nt = 0; nt < 4; nt++) {
                int bc = wn * 32 + nt * 8 + gid;
                bf[nt][0] = Bs[k8 + t4][bc];
                bf[nt][1] = Bs[k8 + t4 + 4][bc];
            }
            #pragma unroll
            for (int mt = 0; mt < 4; mt++) {
                int ar = wm * 64 + mt * 16 + gid;
                float a0 = As[k8 + t4][ar];
                float a1 = As[k8 + t4][ar + 8];
                float a2 = As[k8 + t4 + 4][ar];
                float a3 = As[k8 + t4 + 4][ar + 8];
                #pragma unroll
                for (int nt = 0; nt < 4; nt++)
                    mma_tf32(acc[mt][nt][0], acc[mt][nt][1], acc[mt][nt][2], acc[mt][nt][3],
                             a0, a1, a2, a3, bf[nt][0], bf[nt][1]);
            }
        }
        __syncthreads();
    }

    int is64 = (MODE == 1) ? g_idx64 : 0;
    #pragma unroll
    for (int mt = 0; mt < 4; mt++) {
        #pragma unroll
        for (int half = 0; half < 2; half++) {
            int row = row0 + wm * 64 + mt * 16 + gid + half * 8;
            if (row >= M) continue;
            float* orow;
            if (MODE == 0) {
                orow = C + (size_t)row * ldc;
            } else {
                int bg = idx_at(batch, row, is64);
                int pos = row - starts[bg];
                if (pos >= max_num) continue;
                orow = C + ((size_t)bg * max_num + pos) * N;
            }
            #pragma unroll
            for (int nt = 0; nt < 4; nt++) {
                int col = col0 + wn * 32 + nt * 8 + t4 * 2;
                #pragma unroll
                for (int c = 0; c < 2; c++) {
                    int cc = col + c;
                    if (MODE == 0) {
                        if (cc < N) {
                            orow[cc] = fmaxf(acc[mt][nt][half * 2 + c] + bias[cc], 0.f);
                        } else if (cc < ldc) {
                            orow[cc] = 0.f;
                        }
                    } else {
                        if (cc < N) orow[cc] = acc[mt][nt][half * 2 + c] + bias[cc];
                    }
                }
            }
        }
    }
}

// ---------------- host launcher ----------------
extern "C" void kernel_launch(void* const* d_in, const int* in_sizes, int n_in,
                              void* d_out, int out_size) {
    const float* x     = (const float*)d_in[0];
    const void*  ei    = d_in[1];
    const void*  batch = d_in[2];
    const float* W1 = (const float*)d_in[4];
    const float* b1 = (const float*)d_in[5];
    const float* W2 = (const float*)d_in[6];
    const float* b2 = (const float*)d_in[7];
    const float* W3 = (const float*)d_in[8];
    const float* b3 = (const float*)d_in[9];
    const float* Wf = (const float*)d_in[10];
    const float* bf = (const float*)d_in[11];
    float* out = (float*)d_out;

    int N  = in_sizes[2];
    int E  = in_sizes[1] / 2;
    int F0 = in_sizes[0] / N;        // 54
    int F2 = in_sizes[6] / F0;       // 108
    int F3 = in_sizes[8] / F2;       // 216
    int FO = in_sizes[10] / F3;      // 200
    int max_num = out_size / (NGRAPHS * FO);

    bool fast = (F0 == 54 && F2 == 108 && F3 == 216 && FO == 200);

    float *p_h, *p_agg, *p_dinv;
    int *p_cnt, *p_rowptr, *p_cursor, *p_starts, *p_bsum;
    int2* p_csr;
    cudaGetSymbolAddress((void**)&p_h, g_h);
    cudaGetSymbolAddress((void**)&p_agg, g_agg);
    cudaGetSymbolAddress((void**)&p_dinv, g_dinv);
    cudaGetSymbolAddress((void**)&p_cnt, g_cnt);
    cudaGetSymbolAddress((void**)&p_rowptr, g_rowptr);
    cudaGetSymbolAddress((void**)&p_cursor, g_cursor);
    cudaGetSymbolAddress((void**)&p_csr, g_csr);
    cudaGetSymbolAddress((void**)&p_starts, g_starts);
    cudaGetSymbolAddress((void**)&p_bsum, g_bsum);

    const int T = 256;
    int nb_n = (N + T - 1) / T;
    int nb_e = (E + T - 1) / T;
    int nb_scan = (N + SCAN_BLK - 1) / SCAN_BLK;

    k_init<<<nb_n + 1, T>>>((const int*)ei, batch, p_cnt, p_starts, N);
    {
        dim3 zgrid(32, NGRAPHS);
        k_zero_tail<<<zgrid, T>>>((float4*)out, p_starts, max_num, FO, N);
    }
    k_count<<<nb_e, T>>>(ei, p_cnt, E, N);
    k_scan1<<<nb_scan, T>>>(p_cnt, p_rowptr, p_bsum, N);
    k_scan2<<<1, T>>>(p_bsum, p_rowptr + N, nb_scan);
    k_scan3<<<nb_n, T>>>(p_cnt, p_bsum, p_rowptr, p_cursor, p_dinv, N);
    k_fill<<<nb_e, T>>>(ei, p_dinv, p_cursor, p_csr, E, N);

    int mb = (N + 127) / 128;

    if (fast) {
        // strides: 64 / 112 / 224 floats, pads kept zero
        k_agg_f2<27, 32><<<(N + 7) / 8, T>>>((const float2*)x, 27,
                                             p_rowptr, p_csr, p_dinv,
                                             (float2*)p_agg, N);
        {
            dim3 grid(1, mb);
            k_gemm_ca<0><<<grid, T>>>(p_agg, W1, b1, nullptr, nullptr, p_h,
                                      N, 54, 64, 54, 64, 64, 0);
        }
        k_agg_f4<16, 16><<<(N + 15) / 16, T>>>((const float4*)p_h, 16,
                                               p_rowptr, p_csr, p_dinv,
                                               (float4*)p_agg, N);
        {
            dim3 grid(1, mb);
            k_gemm_ca<0><<<grid, T>>>(p_agg, W2, b2, nullptr, nullptr, p_h,
                                      N, 54, 64, 108, 64, 112, 0);
        }
        k_agg_f4<28, 32><<<(N + 7) / 8, T>>>((const float4*)p_h, 28,
                                             p_rowptr, p_csr, p_dinv,
                                             (float4*)p_agg, N);
        {
            dim3 grid(2, mb);
            k_gemm_ca<0><<<grid, T>>>(p_agg, W3, b3, nullptr, nullptr, p_h,
                                      N, 108, 112, 216, 112, 224, 0);
        }
        {
            dim3 grid(2, mb);
            k_gemm_ca<1><<<grid, T>>>(p_h, Wf, bf, batch, p_starts, out,
                                      N, 216, 224, 200, 224, 200, max_num);
        }
    } else {
        int K1p = ((F0 + 15) / 16) * 16;
        int K3p = ((F2 + 15) / 16) * 16;
        int KfP = ((F3 + 15) / 16) * 16;
        k_aggregate<<<N, ((F0 + 31) / 32) * 32>>>(x, p_rowptr, p_csr, p_dinv, p_agg, F0);
        {
            dim3 grid((F0 + 127) / 128, mb);
            k_gemm_tc<0><<<grid, T>>>(p_agg, W1, b1, nullptr, nullptr, p_h,
                                      N, F0, K1p, F0, F0, F0, 0);
        }
        k_aggregate<<<N, ((F0 + 31) / 32) * 32>>>(p_h, p_rowptr, p_csr, p_dinv, p_agg, F0);
        {
            dim3 grid((F2 + 127) / 128, mb);
            k_gemm_tc<0><<<grid, T>>>(p_agg, W2, b2, nullptr, nullptr, p_h,
                                      N, F0, K1p, F2, F0, F2, 0);
        }
        k_aggregate<<<N, ((F2 + 31) / 32) * 32>>>(p_h, p_rowptr, p_csr, p_dinv, p_agg, F2);
        {
            dim3 grid((F3 + 127) / 128, mb);
            k_gemm_tc<0><<<grid, T>>>(p_agg, W3, b3, nullptr, nullptr, p_h,
                                      N, F2, K3p, F3, F2, F3, 0);
        }
        {
            dim3 grid((FO + 127) / 128, mb);
            k_gemm_tc<1><<<grid, T>>>(p_h, Wf, bf, batch, p_starts, out,
                                      N, F3, KfP, FO, F3, FO, max_num);
        }
    }
}